// round 16
// baseline (speedup 1.0000x reference)
#include <cuda_runtime.h>
#include <math.h>

// ---------------- problem constants ----------------
#define BCLOUD 8
#define PPTS   4096
#define NPTS   (BCLOUD * PPTS)   // 32768
#define KNN    20
#define K2     28                // fp32-scan shortlist size (safety margin over 20)
#define HF     64
#define NCLS   40
#define NEG    0.2f

// ---------------- scratch (device globals; no allocation allowed) ----------
__device__ int    g_idx  [NPTS * KNN];
__device__ int    g_idx2 [NPTS * K2];    // fp32-scan shortlist (local j indices)
__device__ double g_dnorm[NPTS];
__device__ float  g_fnorm[NPTS];
__device__ float  g_x1   [NPTS * HF];
__device__ float  g_x2   [NPTS * HF];
__device__ float  g_x3   [NPTS * HF];
__device__ float  g_cat  [NPTS * 3 * HF];
__device__ float  g_h1   [NPTS * 1024];
__device__ float  g_h2   [NPTS * 256];
__device__ float  g_h3   [NPTS * 128];

// KNN strategy: register-lean fp32 SCAN kernels write a top-K2 shortlist;
// small fp64 REFINE kernels re-rank the K2 candidates exactly (products of
// fp32 are exact in double) under the strict total order (dist, index)
// = jax.lax.top_k. fp32 scan error is orders of magnitude below the
// rank-20 -> rank-K2 distance gap, so the true top-20 is always shortlisted.

// ---------------- phase A (coords): fp32 scan -> top-K2 shortlist ----------
__global__ __launch_bounds__(128) void knn3_scan_kernel(const float* __restrict__ x)
{
    __shared__ float4 s[1024];     // (x, y, z, norm)
    const int b    = blockIdx.y;
    const int li   = blockIdx.x * 128 + threadIdx.x;
    const int base = b * PPTS;

    const float xix = x[(base + li) * 3 + 0];
    const float xiy = x[(base + li) * 3 + 1];
    const float xiz = x[(base + li) * 3 + 2];
    const float ni  = xix * xix + xiy * xiy + xiz * xiz;

    float dk[K2];
    int   ik[K2];
#pragma unroll
    for (int t = 0; t < K2; t++) { dk[t] = INFINITY; ik[t] = 0x7fffffff; }

    for (int j0 = 0; j0 < PPTS; j0 += 1024) {
        __syncthreads();
        for (int r = threadIdx.x; r < 1024; r += 128) {
            float a  = x[(base + j0 + r) * 3 + 0];
            float bb = x[(base + j0 + r) * 3 + 1];
            float c  = x[(base + j0 + r) * 3 + 2];
            s[r] = make_float4(a, bb, c, a * a + bb * bb + c * c);
        }
        __syncthreads();
#pragma unroll 4
        for (int jj = 0; jj < 1024; jj++) {
            float4 t = s[jj];
            float dot  = xix * t.x + xiy * t.y + xiz * t.z;
            float dist = ni + t.w - 2.0f * dot;
            int j = j0 + jj;
            if (dist < dk[K2 - 1] && j != li) {
                float cd = dist; int ci = j;
#pragma unroll
                for (int t2 = 0; t2 < K2; t2++) {
                    if (cd < dk[t2]) {
                        float td = dk[t2]; int ti = ik[t2];
                        dk[t2] = cd; ik[t2] = ci; cd = td; ci = ti;
                    }
                }
            }
        }
    }
#pragma unroll
    for (int t = 0; t < K2; t++) g_idx2[(size_t)(base + li) * K2 + t] = ik[t];
}

// ---------------- phase B (coords): fp64 exact re-rank ---------------------
__global__ __launch_bounds__(256) void knn3_refine_kernel(const float* __restrict__ x)
{
    int p = blockIdx.x * 256 + threadIdx.x;
    const int base = (p / PPTS) * PPTS;

    const double xix = (double)x[p * 3 + 0];
    const double xiy = (double)x[p * 3 + 1];
    const double xiz = (double)x[p * 3 + 2];
    const double ni  = xix * xix + xiy * xiy + xiz * xiz;

    double dk[KNN];
    int    ik[KNN];
#pragma unroll
    for (int t = 0; t < KNN; t++) { dk[t] = 1e300; ik[t] = 0x7fffffff; }

    for (int t = 0; t < K2; t++) {
        int j = g_idx2[(size_t)p * K2 + t];
        double cx = (double)x[(base + j) * 3 + 0];
        double cy = (double)x[(base + j) * 3 + 1];
        double cz = (double)x[(base + j) * 3 + 2];
        double nj  = cx * cx + cy * cy + cz * cz;
        double dot = xix * cx + xiy * cy + xiz * cz;
        double dist = ni + nj - 2.0 * dot;
        bool better = (dist < dk[KNN - 1]) ||
                      (dist == dk[KNN - 1] && j < ik[KNN - 1]);
        if (better) {
            double cd = dist; int ci = j;
#pragma unroll
            for (int t2 = 0; t2 < KNN; t2++) {
                if (cd < dk[t2] || (cd == dk[t2] && ci < ik[t2])) {
                    double td = dk[t2]; int ti = ik[t2];
                    dk[t2] = cd; ik[t2] = ci; cd = td; ci = ti;
                }
            }
        }
    }
#pragma unroll
    for (int t = 0; t < KNN; t++) g_idx[(size_t)p * KNN + t] = base + ik[t];
}

// ---------------- fp64 + fp32 row norms for 64-D features ----------------
__global__ __launch_bounds__(256) void dnorm64_kernel(const float* __restrict__ x)
{
    int p = blockIdx.x * 256 + threadIdx.x;
    const float* row = x + (size_t)p * HF;
    double acc = 0.0;
#pragma unroll
    for (int d = 0; d < HF; d++) {
        double v = (double)row[d];
        acc = fma(v, v, acc);
    }
    g_dnorm[p] = acc;
    g_fnorm[p] = (float)acc;
}

// ---------------- phase A (features): fp32 scan, 8-wide interleave ---------
__global__ __launch_bounds__(128) void knn64_scan_kernel(const float* __restrict__ x)
{
    __shared__ float sx[128][HF];
    __shared__ float sn[128];
    const int b    = blockIdx.y;
    const int li   = blockIdx.x * 128 + threadIdx.x;
    const int base = b * PPTS;

    float xi[HF];
    {
        const float4* row = (const float4*)(x + (size_t)(base + li) * HF);
#pragma unroll
        for (int v = 0; v < 16; v++) {
            float4 t = row[v];
            xi[4 * v + 0] = t.x; xi[4 * v + 1] = t.y;
            xi[4 * v + 2] = t.z; xi[4 * v + 3] = t.w;
        }
    }
    const float ni = g_fnorm[base + li];

    float dk[K2];
    int   ik[K2];
#pragma unroll
    for (int t = 0; t < K2; t++) { dk[t] = INFINITY; ik[t] = 0x7fffffff; }

    for (int j0 = 0; j0 < PPTS; j0 += 128) {
        __syncthreads();
        for (int e = threadIdx.x; e < 128 * 16; e += 128) {
            int r = e >> 4, c = e & 15;
            ((float4*)&sx[r][0])[c] =
                ((const float4*)(x + (size_t)(base + j0 + r) * HF))[c];
        }
        sn[threadIdx.x] = g_fnorm[base + j0 + threadIdx.x];
        __syncthreads();

        for (int jj = 0; jj < 128; jj += 8) {
            float acc[8];
#pragma unroll
            for (int u = 0; u < 8; u++) acc[u] = 0.f;
#pragma unroll
            for (int v = 0; v < 16; v++) {
                float wa = xi[4 * v + 0], wb = xi[4 * v + 1];
                float wc = xi[4 * v + 2], wd = xi[4 * v + 3];
#pragma unroll
                for (int u = 0; u < 8; u++) {
                    float4 t = ((const float4*)&sx[jj + u][0])[v];  // warp bcast
                    acc[u] = fmaf(wa, t.x, acc[u]);
                    acc[u] = fmaf(wb, t.y, acc[u]);
                    acc[u] = fmaf(wc, t.z, acc[u]);
                    acc[u] = fmaf(wd, t.w, acc[u]);
                }
            }
#pragma unroll
            for (int u = 0; u < 8; u++) {
                int j = j0 + jj + u;
                float dist = ni + sn[jj + u] - 2.0f * acc[u];
                if (dist < dk[K2 - 1] && j != li) {
                    float cd = dist; int ci = j;
#pragma unroll
                    for (int t2 = 0; t2 < K2; t2++) {
                        if (cd < dk[t2]) {
                            float td = dk[t2]; int ti = ik[t2];
                            dk[t2] = cd; ik[t2] = ci; cd = td; ci = ti;
                        }
                    }
                }
            }
        }
    }
#pragma unroll
    for (int t = 0; t < K2; t++) g_idx2[(size_t)(base + li) * K2 + t] = ik[t];
}

// ---------------- phase B (features): fp64 exact re-rank -------------------
__global__ __launch_bounds__(256) void knn64_refine_kernel(const float* __restrict__ x)
{
    int p = blockIdx.x * 256 + threadIdx.x;
    const int base = (p / PPTS) * PPTS;

    float xi[HF];
    {
        const float4* row = (const float4*)(x + (size_t)p * HF);
#pragma unroll
        for (int v = 0; v < 16; v++) {
            float4 t = row[v];
            xi[4 * v + 0] = t.x; xi[4 * v + 1] = t.y;
            xi[4 * v + 2] = t.z; xi[4 * v + 3] = t.w;
        }
    }
    const double ni = g_dnorm[p];

    double dk[KNN];
    int    ik[KNN];
#pragma unroll
    for (int t = 0; t < KNN; t++) { dk[t] = 1e300; ik[t] = 0x7fffffff; }

    for (int t = 0; t < K2; t++) {
        int j = g_idx2[(size_t)p * K2 + t];
        const float* row = x + (size_t)(base + j) * HF;
        double dot = 0.0;
#pragma unroll
        for (int d = 0; d < HF; d++)
            dot = fma((double)xi[d], (double)row[d], dot);
        double dist = ni + g_dnorm[base + j] - 2.0 * dot;
        bool better = (dist < dk[KNN - 1]) ||
                      (dist == dk[KNN - 1] && j < ik[KNN - 1]);
        if (better) {
            double cd = dist; int ci = j;
#pragma unroll
            for (int t2 = 0; t2 < KNN; t2++) {
                if (cd < dk[t2] || (cd == dk[t2] && ci < ik[t2])) {
                    double td = dk[t2]; int ti = ik[t2];
                    dk[t2] = cd; ik[t2] = ci; cd = td; ci = ti;
                }
            }
        }
    }
#pragma unroll
    for (int t = 0; t < KNN; t++) g_idx[(size_t)p * KNN + t] = base + ik[t];
}

// ---------------- edge conv, d = 3 ----------------
__global__ __launch_bounds__(256) void edgeconv3_kernel(const float* __restrict__ x,
                                                        const float* __restrict__ W,
                                                        const float* __restrict__ bias,
                                                        float* __restrict__ out)
{
    __shared__ float sW[6 * 64];
    __shared__ float sb[64];
    __shared__ float sxi[4][3];
    __shared__ float sdx[4][KNN][3];
    __shared__ int   sidx[4][KNN];

    const int tid = threadIdx.x;
    const int p0  = blockIdx.x * 4;

    for (int e = tid; e < 384; e += 256) sW[e] = W[e];   // strided (R13 fix)
    if (tid < 64)  sb[tid] = bias[tid];
    if (tid < 12)  sxi[tid / 3][tid % 3] = x[(p0 + tid / 3) * 3 + tid % 3];
    if (tid >= 128 && tid < 128 + 4 * KNN) {
        int e = tid - 128;
        sidx[e / KNN][e % KNN] = g_idx[p0 * KNN + e];
    }
    __syncthreads();

    for (int e = tid; e < 4 * KNN * 3; e += 256) {
        int pp = e / (KNN * 3);
        int r  = e % (KNN * 3);
        int k  = r / 3, d = r % 3;
        sdx[pp][k][d] = x[sidx[pp][k] * 3 + d] - sxi[pp][d];
    }
    __syncthreads();

    const int lp = tid / 64, c = tid % 64;
    const float biasv = sb[c];

    float basev = fmaf(sxi[lp][0], sW[0 * 64 + c], 0.0f);
    basev = fmaf(sxi[lp][1], sW[1 * 64 + c], basev);
    basev = fmaf(sxi[lp][2], sW[2 * 64 + c], basev);

    float m = -INFINITY;
#pragma unroll
    for (int k = 0; k < KNN; k++) {
        float a = basev;
#pragma unroll
        for (int d = 0; d < 3; d++) a = fmaf(sdx[lp][k][d], sW[(3 + d) * 64 + c], a);
        a = __fadd_rn(a, biasv);
        a = (a > 0.f) ? a : NEG * a;
        m = fmaxf(m, a);
    }
    out[(size_t)(p0 + lp) * HF + c] = m;
}

// ---------------- edge conv, d = 64 ----------------
__global__ __launch_bounds__(256) void edgeconv64_kernel(const float* __restrict__ x,
                                                         const float* __restrict__ W,
                                                         const float* __restrict__ bias,
                                                         float* __restrict__ out)
{
    extern __shared__ float smem[];
    float* sW  = smem;                    // 128*64
    float* sxi = sW + 128 * 64;           // 4*64
    float* sdx = sxi + 4 * 64;            // 4*20*64
    int*   sidx = (int*)(sdx + 4 * KNN * 64);   // 4*20

    const int tid = threadIdx.x;
    const int p0  = blockIdx.x * 4;

    for (int e = tid; e < 2048; e += 256)
        ((float4*)sW)[e] = ((const float4*)W)[e];
    {
        int pp = tid / 64, d = tid % 64;
        sxi[pp * 64 + d] = x[(size_t)(p0 + pp) * HF + d];
    }
    if (tid < 4 * KNN) sidx[tid] = g_idx[p0 * KNN + tid];
    __syncthreads();

    for (int e = tid; e < 4 * KNN * 64; e += 256) {
        int pp  = e / (KNN * 64);
        int rem = e % (KNN * 64);
        int k = rem / 64, d = rem % 64;
        sdx[e] = x[(size_t)sidx[pp * KNN + k] * HF + d] - sxi[pp * 64 + d];
    }
    __syncthreads();

    const int lp = tid / 64, c = tid % 64;
    const float biasv = bias[c];

    float basev = fmaf(sxi[lp * 64 + 0], sW[0 * 64 + c], 0.0f);
#pragma unroll
    for (int d = 1; d < 64; d++)
        basev = fmaf(sxi[lp * 64 + d], sW[d * 64 + c], basev);

    float m = -INFINITY;
    for (int k = 0; k < KNN; k++) {
        float a = basev;
        const float* dx = &sdx[(lp * KNN + k) * 64];
#pragma unroll
        for (int d = 0; d < 64; d++)
            a = fmaf(dx[d], sW[(64 + d) * 64 + c], a);
        a = __fadd_rn(a, biasv);
        a = (a > 0.f) ? a : NEG * a;
        m = fmaxf(m, a);
    }
    out[(size_t)(p0 + lp) * HF + c] = m;
}

// ---------------- concat [x1|x2|x3] -> cat ----------------
__global__ __launch_bounds__(256) void concat_kernel()
{
    int e = blockIdx.x * 256 + threadIdx.x;
    if (e >= NPTS * 3 * HF) return;
    int m = e / (3 * HF), c = e % (3 * HF);
    float v;
    if (c < HF)           v = g_x1[(size_t)m * HF + c];
    else if (c < 2 * HF)  v = g_x2[(size_t)m * HF + (c - HF)];
    else                  v = g_x3[(size_t)m * HF + (c - 2 * HF)];
    g_cat[e] = v;
}

// ---------------- tiled SGEMM with fused bias + LeakyReLU ----------------
__global__ __launch_bounds__(256) void gemm_bias_lrelu(const float* __restrict__ A,
                                                       const float* __restrict__ W,
                                                       const float* __restrict__ bias,
                                                       float* __restrict__ C,
                                                       int M, int N, int Kd)
{
    __shared__ float As[16][128];
    __shared__ float Bs[16][64];

    const int tid = threadIdx.x;
    const int tx  = tid & 15;
    const int ty  = tid >> 4;
    const int m0  = blockIdx.y * 128;
    const int n0  = blockIdx.x * 64;

    float acc[8][4];
#pragma unroll
    for (int i = 0; i < 8; i++)
#pragma unroll
        for (int j = 0; j < 4; j++) acc[i][j] = 0.f;

    for (int k0 = 0; k0 < Kd; k0 += 16) {
#pragma unroll
        for (int u = 0; u < 2; u++) {
            int e  = tid + u * 256;
            int r  = e >> 2;
            int c4 = e & 3;
            float4 v = *(const float4*)(A + (size_t)(m0 + r) * Kd + k0 + c4 * 4);
            As[c4 * 4 + 0][r] = v.x; As[c4 * 4 + 1][r] = v.y;
            As[c4 * 4 + 2][r] = v.z; As[c4 * 4 + 3][r] = v.w;
        }
        {
            int r  = tid >> 4;
            int c4 = tid & 15;
            *(float4*)&Bs[r][c4 * 4] =
                *(const float4*)(W + (size_t)(k0 + r) * N + n0 + c4 * 4);
        }
        __syncthreads();
#pragma unroll
        for (int k = 0; k < 16; k++) {
            float a[8];
#pragma unroll
            for (int i = 0; i < 8; i++) a[i] = As[k][ty * 8 + i];
            float4 b4 = *(const float4*)&Bs[k][tx * 4];
            float bb[4] = {b4.x, b4.y, b4.z, b4.w};
#pragma unroll
            for (int i = 0; i < 8; i++)
#pragma unroll
                for (int j = 0; j < 4; j++)
                    acc[i][j] = fmaf(a[i], bb[j], acc[i][j]);
        }
        __syncthreads();
    }

    float4 bv = *(const float4*)(bias + n0 + tx * 4);
    float bb[4] = {bv.x, bv.y, bv.z, bv.w};
#pragma unroll
    for (int i = 0; i < 8; i++) {
        int m = m0 + ty * 8 + i;
        float4 o;
        float v0 = __fadd_rn(acc[i][0], bb[0]); o.x = (v0 > 0.f) ? v0 : NEG * v0;
        float v1 = __fadd_rn(acc[i][1], bb[1]); o.y = (v1 > 0.f) ? v1 : NEG * v1;
        float v2 = __fadd_rn(acc[i][2], bb[2]); o.z = (v2 > 0.f) ? v2 : NEG * v2;
        float v3 = __fadd_rn(acc[i][3], bb[3]); o.w = (v3 > 0.f) ? v3 : NEG * v3;
        *(float4*)(C + (size_t)m * N + n0 + tx * 4) = o;
    }
}

// ---------------- final layer + log_softmax ----------------
__global__ __launch_bounds__(256) void final_kernel(const float* __restrict__ h,
                                                    const float* __restrict__ Wo,
                                                    const float* __restrict__ bo,
                                                    float* __restrict__ out)
{
    __shared__ float sW[128 * NCLS];
    __shared__ float sb[NCLS];
    __shared__ float sh[8][128];

    const int tid = threadIdx.x;
    for (int e = tid; e < 128 * NCLS; e += 256) sW[e] = Wo[e];
    if (tid < NCLS) sb[tid] = bo[tid];

    const int row0 = blockIdx.x * 8;
    for (int e = tid; e < 8 * 128; e += 256)
        sh[e >> 7][e & 127] = h[(size_t)(row0 + (e >> 7)) * 128 + (e & 127)];
    __syncthreads();

    const int w = tid >> 5, lane = tid & 31;
    const int row = row0 + w;

    float v0 = 0.f;
    float v1 = 0.f;
#pragma unroll 8
    for (int d = 0; d < 128; d++) {
        float hv = sh[w][d];
        v0 = fmaf(hv, sW[d * NCLS + lane], v0);
        if (lane < 8) v1 = fmaf(hv, sW[d * NCLS + 32 + lane], v1);
    }
    v0 = __fadd_rn(v0, sb[lane]);
    if (lane < 8) v1 = __fadd_rn(v1, sb[32 + lane]);

    float mx = fmaxf(v0, (lane < 8) ? v1 : -INFINITY);
#pragma unroll
    for (int o = 16; o; o >>= 1) mx = fmaxf(mx, __shfl_xor_sync(0xffffffffu, mx, o));
    float s = expf(v0 - mx) + ((lane < 8) ? expf(v1 - mx) : 0.f);
#pragma unroll
    for (int o = 16; o; o >>= 1) s += __shfl_xor_sync(0xffffffffu, s, o);
    float lse = mx + logf(s);

    out[(size_t)row * NCLS + lane] = v0 - lse;
    if (lane < 8) out[(size_t)row * NCLS + 32 + lane] = v1 - lse;
}

// ---------------- launch ----------------
extern "C" void kernel_launch(void* const* d_in, const int* in_sizes, int n_in,
                              void* d_out, int out_size)
{
    const float* x   = (const float*)d_in[0];
    const float* W1  = (const float*)d_in[2];
    const float* b1  = (const float*)d_in[3];
    const float* W2  = (const float*)d_in[4];
    const float* b2  = (const float*)d_in[5];
    const float* W3  = (const float*)d_in[6];
    const float* b3  = (const float*)d_in[7];
    const float* Wl  = (const float*)d_in[8];
    const float* bl  = (const float*)d_in[9];
    const float* Wm1 = (const float*)d_in[10];
    const float* bm1 = (const float*)d_in[11];
    const float* Wm2 = (const float*)d_in[12];
    const float* bm2 = (const float*)d_in[13];
    const float* Wo  = (const float*)d_in[14];
    const float* bo  = (const float*)d_in[15];
    float* out = (float*)d_out;

    float *px1, *px2, *px3, *pcat, *ph1, *ph2, *ph3;
    cudaGetSymbolAddress((void**)&px1,  g_x1);
    cudaGetSymbolAddress((void**)&px2,  g_x2);
    cudaGetSymbolAddress((void**)&px3,  g_x3);
    cudaGetSymbolAddress((void**)&pcat, g_cat);
    cudaGetSymbolAddress((void**)&ph1,  g_h1);
    cudaGetSymbolAddress((void**)&ph2,  g_h2);
    cudaGetSymbolAddress((void**)&ph3,  g_h3);

    const int EC64_SMEM = (128 * 64 + 4 * 64 + 4 * KNN * 64) * 4 + 4 * KNN * 4;
    cudaFuncSetAttribute(edgeconv64_kernel,
                         cudaFuncAttributeMaxDynamicSharedMemorySize, EC64_SMEM);

    dim3 knn_grid(PPTS / 128, BCLOUD);

    // layer 1
    knn3_scan_kernel<<<knn_grid, 128>>>(x);
    knn3_refine_kernel<<<NPTS / 256, 256>>>(x);
    edgeconv3_kernel<<<NPTS / 4, 256>>>(x, W1, b1, px1);

    // layer 2
    dnorm64_kernel<<<NPTS / 256, 256>>>(px1);
    knn64_scan_kernel<<<knn_grid, 128>>>(px1);
    knn64_refine_kernel<<<NPTS / 256, 256>>>(px1);
    edgeconv64_kernel<<<NPTS / 4, 256, EC64_SMEM>>>(px1, W2, b2, px2);

    // layer 3
    dnorm64_kernel<<<NPTS / 256, 256>>>(px2);
    knn64_scan_kernel<<<knn_grid, 128>>>(px2);
    knn64_refine_kernel<<<NPTS / 256, 256>>>(px2);
    edgeconv64_kernel<<<NPTS / 4, 256, EC64_SMEM>>>(px2, W3, b3, px3);

    // head
    concat_kernel<<<(NPTS * 3 * HF + 255) / 256, 256>>>();
    gemm_bias_lrelu<<<dim3(1024 / 64, NPTS / 128), 256>>>(pcat, Wl,  bl,  ph1, NPTS, 1024, 192);
    gemm_bias_lrelu<<<dim3(256  / 64, NPTS / 128), 256>>>(ph1,  Wm1, bm1, ph2, NPTS, 256, 1024);
    gemm_bias_lrelu<<<dim3(128  / 64, NPTS / 128), 256>>>(ph2,  Wm2, bm2, ph3, NPTS, 128, 256);
    final_kernel<<<NPTS / 8, 256>>>(ph3, Wo, bo, out);
}

// round 17
// speedup vs baseline: 1.1946x; 1.1946x over previous
#include <cuda_runtime.h>
#include <math.h>

// ---------------- problem constants ----------------
#define BCLOUD 8
#define PPTS   4096
#define NPTS   (BCLOUD * PPTS)   // 32768
#define KNN    20
#define K2     28                // fp32-scan shortlist size (safety margin over 20)
#define HF     64
#define NCLS   40
#define NEG    0.2f

// ---------------- scratch (device globals; no allocation allowed) ----------
__device__ int    g_idx  [NPTS * KNN];
__device__ int    g_idx2 [NPTS * K2];    // fp32-scan shortlist (local j indices)
__device__ double g_dnorm[NPTS];
__device__ float  g_fnorm[NPTS];
__device__ float  g_x1   [NPTS * HF];
__device__ float  g_x2   [NPTS * HF];
__device__ float  g_x3   [NPTS * HF];
__device__ float  g_cat  [NPTS * 3 * HF];
__device__ float  g_h1   [NPTS * 1024];
__device__ float  g_h2   [NPTS * 256];
__device__ float  g_h3   [NPTS * 128];

// KNN strategy: register-lean fp32 SCAN kernels write a top-K2 shortlist;
// small fp64 REFINE kernels re-rank the K2 candidates exactly (products of
// fp32 are exact in double) under the strict total order (dist, index)
// = jax.lax.top_k. fp32 scan error is orders of magnitude below the
// rank-20 -> rank-K2 distance gap, so the true top-20 is always shortlisted.

// ---------------- phase A (coords): fp32 scan -> top-K2 shortlist ----------
__global__ __launch_bounds__(128) void knn3_scan_kernel(const float* __restrict__ x)
{
    __shared__ float4 s[1024];     // (x, y, z, norm)
    const int b    = blockIdx.y;
    const int li   = blockIdx.x * 128 + threadIdx.x;
    const int base = b * PPTS;

    const float xix = x[(base + li) * 3 + 0];
    const float xiy = x[(base + li) * 3 + 1];
    const float xiz = x[(base + li) * 3 + 2];
    const float ni  = xix * xix + xiy * xiy + xiz * xiz;

    float dk[K2];
    int   ik[K2];
#pragma unroll
    for (int t = 0; t < K2; t++) { dk[t] = INFINITY; ik[t] = 0x7fffffff; }

    for (int j0 = 0; j0 < PPTS; j0 += 1024) {
        __syncthreads();
        for (int r = threadIdx.x; r < 1024; r += 128) {
            float a  = x[(base + j0 + r) * 3 + 0];
            float bb = x[(base + j0 + r) * 3 + 1];
            float c  = x[(base + j0 + r) * 3 + 2];
            s[r] = make_float4(a, bb, c, a * a + bb * bb + c * c);
        }
        __syncthreads();
#pragma unroll 4
        for (int jj = 0; jj < 1024; jj++) {
            float4 t = s[jj];
            float dot  = xix * t.x + xiy * t.y + xiz * t.z;
            float dist = ni + t.w - 2.0f * dot;
            int j = j0 + jj;
            if (dist < dk[K2 - 1] && j != li) {
                float cd = dist; int ci = j;
#pragma unroll
                for (int t2 = 0; t2 < K2; t2++) {
                    if (cd < dk[t2]) {
                        float td = dk[t2]; int ti = ik[t2];
                        dk[t2] = cd; ik[t2] = ci; cd = td; ci = ti;
                    }
                }
            }
        }
    }
#pragma unroll
    for (int t = 0; t < K2; t++) g_idx2[(size_t)(base + li) * K2 + t] = ik[t];
}

// ---------------- phase B (coords): fp64 exact re-rank ---------------------
__global__ __launch_bounds__(256) void knn3_refine_kernel(const float* __restrict__ x)
{
    int p = blockIdx.x * 256 + threadIdx.x;
    const int base = (p / PPTS) * PPTS;

    const double xix = (double)x[p * 3 + 0];
    const double xiy = (double)x[p * 3 + 1];
    const double xiz = (double)x[p * 3 + 2];
    const double ni  = xix * xix + xiy * xiy + xiz * xiz;

    double dk[KNN];
    int    ik[KNN];
#pragma unroll
    for (int t = 0; t < KNN; t++) { dk[t] = 1e300; ik[t] = 0x7fffffff; }

    for (int t = 0; t < K2; t++) {
        int j = g_idx2[(size_t)p * K2 + t];
        double cx = (double)x[(base + j) * 3 + 0];
        double cy = (double)x[(base + j) * 3 + 1];
        double cz = (double)x[(base + j) * 3 + 2];
        double nj  = cx * cx + cy * cy + cz * cz;
        double dot = xix * cx + xiy * cy + xiz * cz;
        double dist = ni + nj - 2.0 * dot;
        bool better = (dist < dk[KNN - 1]) ||
                      (dist == dk[KNN - 1] && j < ik[KNN - 1]);
        if (better) {
            double cd = dist; int ci = j;
#pragma unroll
            for (int t2 = 0; t2 < KNN; t2++) {
                if (cd < dk[t2] || (cd == dk[t2] && ci < ik[t2])) {
                    double td = dk[t2]; int ti = ik[t2];
                    dk[t2] = cd; ik[t2] = ci; cd = td; ci = ti;
                }
            }
        }
    }
#pragma unroll
    for (int t = 0; t < KNN; t++) g_idx[(size_t)p * KNN + t] = base + ik[t];
}

// ---------------- fp64 + fp32 row norms for 64-D features ----------------
__global__ __launch_bounds__(256) void dnorm64_kernel(const float* __restrict__ x)
{
    int p = blockIdx.x * 256 + threadIdx.x;
    const float* row = x + (size_t)p * HF;
    double acc = 0.0;
#pragma unroll
    for (int d = 0; d < HF; d++) {
        double v = (double)row[d];
        acc = fma(v, v, acc);
    }
    g_dnorm[p] = acc;
    g_fnorm[p] = (float)acc;
}

// ---------------- phase A (features): fp32 scan, 4-wide (R15 proven) -------
__global__ __launch_bounds__(128) void knn64_scan_kernel(const float* __restrict__ x)
{
    __shared__ float sx[128][HF];
    __shared__ float sn[128];
    const int b    = blockIdx.y;
    const int li   = blockIdx.x * 128 + threadIdx.x;
    const int base = b * PPTS;

    float xi[HF];
    {
        const float4* row = (const float4*)(x + (size_t)(base + li) * HF);
#pragma unroll
        for (int v = 0; v < 16; v++) {
            float4 t = row[v];
            xi[4 * v + 0] = t.x; xi[4 * v + 1] = t.y;
            xi[4 * v + 2] = t.z; xi[4 * v + 3] = t.w;
        }
    }
    const float ni = g_fnorm[base + li];

    float dk[K2];
    int   ik[K2];
#pragma unroll
    for (int t = 0; t < K2; t++) { dk[t] = INFINITY; ik[t] = 0x7fffffff; }

    for (int j0 = 0; j0 < PPTS; j0 += 128) {
        __syncthreads();
        for (int e = threadIdx.x; e < 128 * 16; e += 128) {
            int r = e >> 4, c = e & 15;
            ((float4*)&sx[r][0])[c] =
                ((const float4*)(x + (size_t)(base + j0 + r) * HF))[c];
        }
        sn[threadIdx.x] = g_fnorm[base + j0 + threadIdx.x];
        __syncthreads();

        for (int jj = 0; jj < 128; jj += 4) {
            float a0 = 0.f, a1 = 0.f, a2 = 0.f, a3 = 0.f;
            const float4* r0 = (const float4*)&sx[jj + 0][0];
            const float4* r1 = (const float4*)&sx[jj + 1][0];
            const float4* r2 = (const float4*)&sx[jj + 2][0];
            const float4* r3 = (const float4*)&sx[jj + 3][0];
#pragma unroll
            for (int v = 0; v < 16; v++) {
                float4 t0 = r0[v], t1 = r1[v], t2 = r2[v], t3 = r3[v];
                float wa = xi[4 * v + 0], wb = xi[4 * v + 1];
                float wc = xi[4 * v + 2], wd = xi[4 * v + 3];
                a0 = fmaf(wa, t0.x, a0); a0 = fmaf(wb, t0.y, a0);
                a0 = fmaf(wc, t0.z, a0); a0 = fmaf(wd, t0.w, a0);
                a1 = fmaf(wa, t1.x, a1); a1 = fmaf(wb, t1.y, a1);
                a1 = fmaf(wc, t1.z, a1); a1 = fmaf(wd, t1.w, a1);
                a2 = fmaf(wa, t2.x, a2); a2 = fmaf(wb, t2.y, a2);
                a2 = fmaf(wc, t2.z, a2); a2 = fmaf(wd, t2.w, a2);
                a3 = fmaf(wa, t3.x, a3); a3 = fmaf(wb, t3.y, a3);
                a3 = fmaf(wc, t3.z, a3); a3 = fmaf(wd, t3.w, a3);
            }
            float dots[4] = {a0, a1, a2, a3};
#pragma unroll
            for (int q = 0; q < 4; q++) {
                int j = j0 + jj + q;
                float dist = ni + sn[jj + q] - 2.0f * dots[q];
                if (dist < dk[K2 - 1] && j != li) {
                    float cd = dist; int ci = j;
#pragma unroll
                    for (int t2 = 0; t2 < K2; t2++) {
                        if (cd < dk[t2]) {
                            float td = dk[t2]; int ti = ik[t2];
                            dk[t2] = cd; ik[t2] = ci; cd = td; ci = ti;
                        }
                    }
                }
            }
        }
    }
#pragma unroll
    for (int t = 0; t < K2; t++) g_idx2[(size_t)(base + li) * K2 + t] = ik[t];
}

// ---------------- phase B (features): fp64 exact re-rank -------------------
__global__ __launch_bounds__(256) void knn64_refine_kernel(const float* __restrict__ x)
{
    int p = blockIdx.x * 256 + threadIdx.x;
    const int base = (p / PPTS) * PPTS;

    float xi[HF];
    {
        const float4* row = (const float4*)(x + (size_t)p * HF);
#pragma unroll
        for (int v = 0; v < 16; v++) {
            float4 t = row[v];
            xi[4 * v + 0] = t.x; xi[4 * v + 1] = t.y;
            xi[4 * v + 2] = t.z; xi[4 * v + 3] = t.w;
        }
    }
    const double ni = g_dnorm[p];

    double dk[KNN];
    int    ik[KNN];
#pragma unroll
    for (int t = 0; t < KNN; t++) { dk[t] = 1e300; ik[t] = 0x7fffffff; }

    for (int t = 0; t < K2; t++) {
        int j = g_idx2[(size_t)p * K2 + t];
        const float* row = x + (size_t)(base + j) * HF;
        double dot = 0.0;
#pragma unroll
        for (int d = 0; d < HF; d++)
            dot = fma((double)xi[d], (double)row[d], dot);
        double dist = ni + g_dnorm[base + j] - 2.0 * dot;
        bool better = (dist < dk[KNN - 1]) ||
                      (dist == dk[KNN - 1] && j < ik[KNN - 1]);
        if (better) {
            double cd = dist; int ci = j;
#pragma unroll
            for (int t2 = 0; t2 < KNN; t2++) {
                if (cd < dk[t2] || (cd == dk[t2] && ci < ik[t2])) {
                    double td = dk[t2]; int ti = ik[t2];
                    dk[t2] = cd; ik[t2] = ci; cd = td; ci = ti;
                }
            }
        }
    }
#pragma unroll
    for (int t = 0; t < KNN; t++) g_idx[(size_t)p * KNN + t] = base + ik[t];
}

// ---------------- edge conv, d = 3 ----------------
__global__ __launch_bounds__(256) void edgeconv3_kernel(const float* __restrict__ x,
                                                        const float* __restrict__ W,
                                                        const float* __restrict__ bias,
                                                        float* __restrict__ out)
{
    __shared__ float sW[6 * 64];
    __shared__ float sb[64];
    __shared__ float sxi[4][3];
    __shared__ float sdx[4][KNN][3];
    __shared__ int   sidx[4][KNN];

    const int tid = threadIdx.x;
    const int p0  = blockIdx.x * 4;

    for (int e = tid; e < 384; e += 256) sW[e] = W[e];   // strided (R13 fix)
    if (tid < 64)  sb[tid] = bias[tid];
    if (tid < 12)  sxi[tid / 3][tid % 3] = x[(p0 + tid / 3) * 3 + tid % 3];
    if (tid >= 128 && tid < 128 + 4 * KNN) {
        int e = tid - 128;
        sidx[e / KNN][e % KNN] = g_idx[p0 * KNN + e];
    }
    __syncthreads();

    for (int e = tid; e < 4 * KNN * 3; e += 256) {
        int pp = e / (KNN * 3);
        int r  = e % (KNN * 3);
        int k  = r / 3, d = r % 3;
        sdx[pp][k][d] = x[sidx[pp][k] * 3 + d] - sxi[pp][d];
    }
    __syncthreads();

    const int lp = tid / 64, c = tid % 64;
    const float biasv = sb[c];

    float basev = fmaf(sxi[lp][0], sW[0 * 64 + c], 0.0f);
    basev = fmaf(sxi[lp][1], sW[1 * 64 + c], basev);
    basev = fmaf(sxi[lp][2], sW[2 * 64 + c], basev);

    float m = -INFINITY;
#pragma unroll
    for (int k = 0; k < KNN; k++) {
        float a = basev;
#pragma unroll
        for (int d = 0; d < 3; d++) a = fmaf(sdx[lp][k][d], sW[(3 + d) * 64 + c], a);
        a = __fadd_rn(a, biasv);
        a = (a > 0.f) ? a : NEG * a;
        m = fmaxf(m, a);
    }
    out[(size_t)(p0 + lp) * HF + c] = m;
}

// ---------------- edge conv, d = 64 ----------------
__global__ __launch_bounds__(256) void edgeconv64_kernel(const float* __restrict__ x,
                                                         const float* __restrict__ W,
                                                         const float* __restrict__ bias,
                                                         float* __restrict__ out)
{
    extern __shared__ float smem[];
    float* sW  = smem;                    // 128*64
    float* sxi = sW + 128 * 64;           // 4*64
    float* sdx = sxi + 4 * 64;            // 4*20*64
    int*   sidx = (int*)(sdx + 4 * KNN * 64);   // 4*20

    const int tid = threadIdx.x;
    const int p0  = blockIdx.x * 4;

    for (int e = tid; e < 2048; e += 256)
        ((float4*)sW)[e] = ((const float4*)W)[e];
    {
        int pp = tid / 64, d = tid % 64;
        sxi[pp * 64 + d] = x[(size_t)(p0 + pp) * HF + d];
    }
    if (tid < 4 * KNN) sidx[tid] = g_idx[p0 * KNN + tid];
    __syncthreads();

    for (int e = tid; e < 4 * KNN * 64; e += 256) {
        int pp  = e / (KNN * 64);
        int rem = e % (KNN * 64);
        int k = rem / 64, d = rem % 64;
        sdx[e] = x[(size_t)sidx[pp * KNN + k] * HF + d] - sxi[pp * 64 + d];
    }
    __syncthreads();

    const int lp = tid / 64, c = tid % 64;
    const float biasv = bias[c];

    float basev = fmaf(sxi[lp * 64 + 0], sW[0 * 64 + c], 0.0f);
#pragma unroll
    for (int d = 1; d < 64; d++)
        basev = fmaf(sxi[lp * 64 + d], sW[d * 64 + c], basev);

    float m = -INFINITY;
    for (int k = 0; k < KNN; k++) {
        float a = basev;
        const float* dx = &sdx[(lp * KNN + k) * 64];
#pragma unroll
        for (int d = 0; d < 64; d++)
            a = fmaf(dx[d], sW[(64 + d) * 64 + c], a);
        a = __fadd_rn(a, biasv);
        a = (a > 0.f) ? a : NEG * a;
        m = fmaxf(m, a);
    }
    out[(size_t)(p0 + lp) * HF + c] = m;
}

// ---------------- concat [x1|x2|x3] -> cat ----------------
__global__ __launch_bounds__(256) void concat_kernel()
{
    int e = blockIdx.x * 256 + threadIdx.x;
    if (e >= NPTS * 3 * HF) return;
    int m = e / (3 * HF), c = e % (3 * HF);
    float v;
    if (c < HF)           v = g_x1[(size_t)m * HF + c];
    else if (c < 2 * HF)  v = g_x2[(size_t)m * HF + (c - HF)];
    else                  v = g_x3[(size_t)m * HF + (c - 2 * HF)];
    g_cat[e] = v;
}

// ---------------- tiled SGEMM with fused bias + LeakyReLU ----------------
__global__ __launch_bounds__(256) void gemm_bias_lrelu(const float* __restrict__ A,
                                                       const float* __restrict__ W,
                                                       const float* __restrict__ bias,
                                                       float* __restrict__ C,
                                                       int M, int N, int Kd)
{
    __shared__ float As[16][128];
    __shared__ float Bs[16][64];

    const int tid = threadIdx.x;
    const int tx  = tid & 15;
    const int ty  = tid >> 4;
    const int m0  = blockIdx.y * 128;
    const int n0  = blockIdx.x * 64;

    float acc[8][4];
#pragma unroll
    for (int i = 0; i < 8; i++)
#pragma unroll
        for (int j = 0; j < 4; j++) acc[i][j] = 0.f;

    for (int k0 = 0; k0 < Kd; k0 += 16) {
#pragma unroll
        for (int u = 0; u < 2; u++) {
            int e  = tid + u * 256;
            int r  = e >> 2;
            int c4 = e & 3;
            float4 v = *(const float4*)(A + (size_t)(m0 + r) * Kd + k0 + c4 * 4);
            As[c4 * 4 + 0][r] = v.x; As[c4 * 4 + 1][r] = v.y;
            As[c4 * 4 + 2][r] = v.z; As[c4 * 4 + 3][r] = v.w;
        }
        {
            int r  = tid >> 4;
            int c4 = tid & 15;
            *(float4*)&Bs[r][c4 * 4] =
                *(const float4*)(W + (size_t)(k0 + r) * N + n0 + c4 * 4);
        }
        __syncthreads();
#pragma unroll
        for (int k = 0; k < 16; k++) {
            float a[8];
#pragma unroll
            for (int i = 0; i < 8; i++) a[i] = As[k][ty * 8 + i];
            float4 b4 = *(const float4*)&Bs[k][tx * 4];
            float bb[4] = {b4.x, b4.y, b4.z, b4.w};
#pragma unroll
            for (int i = 0; i < 8; i++)
#pragma unroll
                for (int j = 0; j < 4; j++)
                    acc[i][j] = fmaf(a[i], bb[j], acc[i][j]);
        }
        __syncthreads();
    }

    float4 bv = *(const float4*)(bias + n0 + tx * 4);
    float bb[4] = {bv.x, bv.y, bv.z, bv.w};
#pragma unroll
    for (int i = 0; i < 8; i++) {
        int m = m0 + ty * 8 + i;
        float4 o;
        float v0 = __fadd_rn(acc[i][0], bb[0]); o.x = (v0 > 0.f) ? v0 : NEG * v0;
        float v1 = __fadd_rn(acc[i][1], bb[1]); o.y = (v1 > 0.f) ? v1 : NEG * v1;
        float v2 = __fadd_rn(acc[i][2], bb[2]); o.z = (v2 > 0.f) ? v2 : NEG * v2;
        float v3 = __fadd_rn(acc[i][3], bb[3]); o.w = (v3 > 0.f) ? v3 : NEG * v3;
        *(float4*)(C + (size_t)m * N + n0 + tx * 4) = o;
    }
}

// ---------------- final layer + log_softmax ----------------
__global__ __launch_bounds__(256) void final_kernel(const float* __restrict__ h,
                                                    const float* __restrict__ Wo,
                                                    const float* __restrict__ bo,
                                                    float* __restrict__ out)
{
    __shared__ float sW[128 * NCLS];
    __shared__ float sb[NCLS];
    __shared__ float sh[8][128];

    const int tid = threadIdx.x;
    for (int e = tid; e < 128 * NCLS; e += 256) sW[e] = Wo[e];
    if (tid < NCLS) sb[tid] = bo[tid];

    const int row0 = blockIdx.x * 8;
    for (int e = tid; e < 8 * 128; e += 256)
        sh[e >> 7][e & 127] = h[(size_t)(row0 + (e >> 7)) * 128 + (e & 127)];
    __syncthreads();

    const int w = tid >> 5, lane = tid & 31;
    const int row = row0 + w;

    float v0 = 0.f;
    float v1 = 0.f;
#pragma unroll 8
    for (int d = 0; d < 128; d++) {
        float hv = sh[w][d];
        v0 = fmaf(hv, sW[d * NCLS + lane], v0);
        if (lane < 8) v1 = fmaf(hv, sW[d * NCLS + 32 + lane], v1);
    }
    v0 = __fadd_rn(v0, sb[lane]);
    if (lane < 8) v1 = __fadd_rn(v1, sb[32 + lane]);

    float mx = fmaxf(v0, (lane < 8) ? v1 : -INFINITY);
#pragma unroll
    for (int o = 16; o; o >>= 1) mx = fmaxf(mx, __shfl_xor_sync(0xffffffffu, mx, o));
    float s = expf(v0 - mx) + ((lane < 8) ? expf(v1 - mx) : 0.f);
#pragma unroll
    for (int o = 16; o; o >>= 1) s += __shfl_xor_sync(0xffffffffu, s, o);
    float lse = mx + logf(s);

    out[(size_t)row * NCLS + lane] = v0 - lse;
    if (lane < 8) out[(size_t)row * NCLS + 32 + lane] = v1 - lse;
}

// ---------------- launch ----------------
extern "C" void kernel_launch(void* const* d_in, const int* in_sizes, int n_in,
                              void* d_out, int out_size)
{
    const float* x   = (const float*)d_in[0];
    const float* W1  = (const float*)d_in[2];
    const float* b1  = (const float*)d_in[3];
    const float* W2  = (const float*)d_in[4];
    const float* b2  = (const float*)d_in[5];
    const float* W3  = (const float*)d_in[6];
    const float* b3  = (const float*)d_in[7];
    const float* Wl  = (const float*)d_in[8];
    const float* bl  = (const float*)d_in[9];
    const float* Wm1 = (const float*)d_in[10];
    const float* bm1 = (const float*)d_in[11];
    const float* Wm2 = (const float*)d_in[12];
    const float* bm2 = (const float*)d_in[13];
    const float* Wo  = (const float*)d_in[14];
    const float* bo  = (const float*)d_in[15];
    float* out = (float*)d_out;

    float *px1, *px2, *px3, *pcat, *ph1, *ph2, *ph3;
    cudaGetSymbolAddress((void**)&px1,  g_x1);
    cudaGetSymbolAddress((void**)&px2,  g_x2);
    cudaGetSymbolAddress((void**)&px3,  g_x3);
    cudaGetSymbolAddress((void**)&pcat, g_cat);
    cudaGetSymbolAddress((void**)&ph1,  g_h1);
    cudaGetSymbolAddress((void**)&ph2,  g_h2);
    cudaGetSymbolAddress((void**)&ph3,  g_h3);

    const int EC64_SMEM = (128 * 64 + 4 * 64 + 4 * KNN * 64) * 4 + 4 * KNN * 4;
    cudaFuncSetAttribute(edgeconv64_kernel,
                         cudaFuncAttributeMaxDynamicSharedMemorySize, EC64_SMEM);

    dim3 knn_grid(PPTS / 128, BCLOUD);

    // layer 1
    knn3_scan_kernel<<<knn_grid, 128>>>(x);
    knn3_refine_kernel<<<NPTS / 256, 256>>>(x);
    edgeconv3_kernel<<<NPTS / 4, 256>>>(x, W1, b1, px1);

    // layer 2
    dnorm64_kernel<<<NPTS / 256, 256>>>(px1);
    knn64_scan_kernel<<<knn_grid, 128>>>(px1);
    knn64_refine_kernel<<<NPTS / 256, 256>>>(px1);
    edgeconv64_kernel<<<NPTS / 4, 256, EC64_SMEM>>>(px1, W2, b2, px2);

    // layer 3
    dnorm64_kernel<<<NPTS / 256, 256>>>(px2);
    knn64_scan_kernel<<<knn_grid, 128>>>(px2);
    knn64_refine_kernel<<<NPTS / 256, 256>>>(px2);
    edgeconv64_kernel<<<NPTS / 4, 256, EC64_SMEM>>>(px2, W3, b3, px3);

    // head
    concat_kernel<<<(NPTS * 3 * HF + 255) / 256, 256>>>();
    gemm_bias_lrelu<<<dim3(1024 / 64, NPTS / 128), 256>>>(pcat, Wl,  bl,  ph1, NPTS, 1024, 192);
    gemm_bias_lrelu<<<dim3(256  / 64, NPTS / 128), 256>>>(ph1,  Wm1, bm1, ph2, NPTS, 256, 1024);
    gemm_bias_lrelu<<<dim3(128  / 64, NPTS / 128), 256>>>(ph2,  Wm2, bm2, ph3, NPTS, 128, 256);
    final_kernel<<<NPTS / 8, 256>>>(ph3, Wo, bo, out);
}